// round 2
// baseline (speedup 1.0000x reference)
#include <cuda_runtime.h>

// LIF timestep, elementwise over N = 16*56*56*256 = 12,845,056 elements.
// Inputs (metadata order): impulse, mem, mem_acc, refrac_until, spikecounts
// Output: 6 stacked planes of N floats:
//   [spikes, mem_out, mem_acc_out, refrac_out, counts_out, spiketrain]
//
// HBM-bound streaming kernel: touch-once data -> evict-first cache hints,
// 2 float4 per thread front-batched (MLP=10) to keep the L1tex queue deep.

#define V_THRESH 1.0f
#define TIME_C 0.5f
#define REFRAC_SET 2.5f   // TIME + TAU_REFRAC

__device__ __forceinline__ void lif_step(const float4& imp, const float4& m,
                                         const float4& ma, const float4& ru,
                                         const float4& sc,
                                         float4& o_spk, float4& o_mem,
                                         float4& o_acc, float4& o_ref,
                                         float4& o_cnt, float4& o_trn) {
    #pragma unroll
    for (int l = 0; l < 4; ++l) {
        const float impv = (&imp.x)[l];
        const float memv = (&m.x)[l];
        const float accv = (&ma.x)[l];
        const float ruv  = (&ru.x)[l];
        const float scv  = (&sc.x)[l];

        const float masked  = (ruv > TIME_C) ? 0.0f : impv;
        const float new_mem = memv + masked;
        const float new_acc = accv + masked;

        const bool  fired  = (new_mem >= V_THRESH);
        const float spikes = fired ? V_THRESH : 0.0f;

        const float mem_out = fired ? (new_mem - V_THRESH) : new_mem;
        const float ref_out = fired ? REFRAC_SET : ruv;
        const float cnt_out = scv + (fired ? 1.0f : 0.0f);
        const float trn_out = spikes * TIME_C;

        (&o_spk.x)[l] = spikes;
        (&o_mem.x)[l] = mem_out;
        (&o_acc.x)[l] = new_acc;
        (&o_ref.x)[l] = ref_out;
        (&o_cnt.x)[l] = cnt_out;
        (&o_trn.x)[l] = trn_out;
    }
}

__global__ void __launch_bounds__(256, 8)
spike_layer_kernel(const float4* __restrict__ impulse,
                   const float4* __restrict__ mem,
                   const float4* __restrict__ mem_acc,
                   const float4* __restrict__ refrac_until,
                   const float4* __restrict__ spikecounts,
                   float4* __restrict__ out,   // 6 planes of n4 float4 each
                   int n4) {
    // Each block owns 512 consecutive float4; each thread 2 (stride 256).
    const int i0 = blockIdx.x * 512 + threadIdx.x;
    const int i1 = i0 + 256;
    // n4 % 512 == 0 for this problem, but keep a cheap guard for safety.
    if (i1 >= n4) {
        if (i0 >= n4) return;
        const float4 imp = __ldcs(&impulse[i0]);
        const float4 m   = __ldcs(&mem[i0]);
        const float4 ma  = __ldcs(&mem_acc[i0]);
        const float4 ru  = __ldcs(&refrac_until[i0]);
        const float4 sc  = __ldcs(&spikecounts[i0]);
        float4 a,b,c,d,e,f;
        lif_step(imp,m,ma,ru,sc,a,b,c,d,e,f);
        __stcs(&out[0*(size_t)n4 + i0], a);
        __stcs(&out[1*(size_t)n4 + i0], b);
        __stcs(&out[2*(size_t)n4 + i0], c);
        __stcs(&out[3*(size_t)n4 + i0], d);
        __stcs(&out[4*(size_t)n4 + i0], e);
        __stcs(&out[5*(size_t)n4 + i0], f);
        return;
    }

    // Front-batch all 10 loads (MLP = 10)
    const float4 imp0 = __ldcs(&impulse[i0]);
    const float4 imp1 = __ldcs(&impulse[i1]);
    const float4 m0   = __ldcs(&mem[i0]);
    const float4 m1   = __ldcs(&mem[i1]);
    const float4 ma0  = __ldcs(&mem_acc[i0]);
    const float4 ma1  = __ldcs(&mem_acc[i1]);
    const float4 ru0  = __ldcs(&refrac_until[i0]);
    const float4 ru1  = __ldcs(&refrac_until[i1]);
    const float4 sc0  = __ldcs(&spikecounts[i0]);
    const float4 sc1  = __ldcs(&spikecounts[i1]);

    float4 a0,b0,c0,d0,e0,f0;
    float4 a1,b1,c1,d1,e1,f1;
    lif_step(imp0,m0,ma0,ru0,sc0,a0,b0,c0,d0,e0,f0);
    lif_step(imp1,m1,ma1,ru1,sc1,a1,b1,c1,d1,e1,f1);

    // Stores grouped per plane (both warp-coalesced halves back to back)
    __stcs(&out[0*(size_t)n4 + i0], a0);
    __stcs(&out[0*(size_t)n4 + i1], a1);
    __stcs(&out[1*(size_t)n4 + i0], b0);
    __stcs(&out[1*(size_t)n4 + i1], b1);
    __stcs(&out[2*(size_t)n4 + i0], c0);
    __stcs(&out[2*(size_t)n4 + i1], c1);
    __stcs(&out[3*(size_t)n4 + i0], d0);
    __stcs(&out[3*(size_t)n4 + i1], d1);
    __stcs(&out[4*(size_t)n4 + i0], e0);
    __stcs(&out[4*(size_t)n4 + i1], e1);
    __stcs(&out[5*(size_t)n4 + i0], f0);
    __stcs(&out[5*(size_t)n4 + i1], f1);
}

extern "C" void kernel_launch(void* const* d_in, const int* in_sizes, int n_in,
                              void* d_out, int out_size) {
    const float4* impulse      = (const float4*)d_in[0];
    const float4* mem          = (const float4*)d_in[1];
    const float4* mem_acc      = (const float4*)d_in[2];
    const float4* refrac_until = (const float4*)d_in[3];
    const float4* spikecounts  = (const float4*)d_in[4];
    float4* out = (float4*)d_out;

    const int n  = in_sizes[0];       // 12,845,056
    const int n4 = n / 4;             // 3,211,264  (divisible by 512)

    const int threads = 256;
    const int blocks  = (n4 + threads * 2 - 1) / (threads * 2);   // 6272
    spike_layer_kernel<<<blocks, threads>>>(impulse, mem, mem_acc,
                                            refrac_until, spikecounts,
                                            out, n4);
}

// round 3
// speedup vs baseline: 1.2412x; 1.2412x over previous
#include <cuda_runtime.h>

// LIF timestep, elementwise over N = 16*56*56*256 = 12,845,056 elements.
// Inputs (metadata order): impulse, mem, mem_acc, refrac_until, spikecounts
// Output: 6 stacked planes of N floats:
//   [spikes, mem_out, mem_acc_out, refrac_out, counts_out, spiketrain]
//
// R1 structure (1 float4/thread, front-batched MLP=5) + streaming stores.
// R2 post-mortem: ILP=2 under a 32-reg launch_bounds cap serialized the
// loads and regressed; reverted. Single change this round: __stcs stores.

#define V_THRESH 1.0f
#define TIME_C 0.5f
#define REFRAC_SET 2.5f   // TIME + TAU_REFRAC

__global__ void __launch_bounds__(256)
spike_layer_kernel(const float4* __restrict__ impulse,
                   const float4* __restrict__ mem,
                   const float4* __restrict__ mem_acc,
                   const float4* __restrict__ refrac_until,
                   const float4* __restrict__ spikecounts,
                   float4* __restrict__ out,   // 6 planes of n4 float4 each
                   int n4) {
    int i = blockIdx.x * blockDim.x + threadIdx.x;
    if (i >= n4) return;

    // Front-batch all 5 loads (MLP = 5, overlap DRAM latency)
    const float4 imp = __ldg(&impulse[i]);
    const float4 m   = __ldg(&mem[i]);
    const float4 ma  = __ldg(&mem_acc[i]);
    const float4 ru  = __ldg(&refrac_until[i]);
    const float4 sc  = __ldg(&spikecounts[i]);

    float4 o_spk, o_mem, o_acc, o_ref, o_cnt, o_trn;

    #pragma unroll
    for (int l = 0; l < 4; ++l) {
        const float impv = (&imp.x)[l];
        const float memv = (&m.x)[l];
        const float accv = (&ma.x)[l];
        const float ruv  = (&ru.x)[l];
        const float scv  = (&sc.x)[l];

        // refractory mask on input
        const float masked  = (ruv > TIME_C) ? 0.0f : impv;
        const float new_mem = memv + masked;
        const float new_acc = accv + masked;

        // linear activation: spikes in {0, V_THRESH}
        const bool  fired  = (new_mem >= V_THRESH);
        const float spikes = fired ? V_THRESH : 0.0f;

        // reset by subtraction (spikes<0 branch unreachable: spikes>=0)
        const float mem_out = fired ? (new_mem - V_THRESH) : new_mem;
        const float ref_out = fired ? REFRAC_SET : ruv;
        const float cnt_out = scv + (fired ? 1.0f : 0.0f);
        const float trn_out = spikes * TIME_C;

        (&o_spk.x)[l] = spikes;
        (&o_mem.x)[l] = mem_out;
        (&o_acc.x)[l] = new_acc;
        (&o_ref.x)[l] = ref_out;
        (&o_cnt.x)[l] = cnt_out;
        (&o_trn.x)[l] = trn_out;
    }

    // 6 output planes; write-once data -> evict-first streaming stores
    __stcs(&out[0 * (size_t)n4 + i], o_spk);
    __stcs(&out[1 * (size_t)n4 + i], o_mem);
    __stcs(&out[2 * (size_t)n4 + i], o_acc);
    __stcs(&out[3 * (size_t)n4 + i], o_ref);
    __stcs(&out[4 * (size_t)n4 + i], o_cnt);
    __stcs(&out[5 * (size_t)n4 + i], o_trn);
}

extern "C" void kernel_launch(void* const* d_in, const int* in_sizes, int n_in,
                              void* d_out, int out_size) {
    const float4* impulse      = (const float4*)d_in[0];
    const float4* mem          = (const float4*)d_in[1];
    const float4* mem_acc      = (const float4*)d_in[2];
    const float4* refrac_until = (const float4*)d_in[3];
    const float4* spikecounts  = (const float4*)d_in[4];
    float4* out = (float4*)d_out;

    const int n  = in_sizes[0];       // 12,845,056 (divisible by 4)
    const int n4 = n / 4;             // 3,211,264

    const int threads = 256;
    const int blocks  = (n4 + threads - 1) / threads;   // 12544
    spike_layer_kernel<<<blocks, threads>>>(impulse, mem, mem_acc,
                                            refrac_until, spikecounts,
                                            out, n4);
}